// round 4
// baseline (speedup 1.0000x reference)
#include <cuda_runtime.h>
#include <float.h>

#define BN 4096
#define KN 32768
#define DN 128
#define HN 3
#define NSPLIT 16
#define MT 128
#define KT 128

// scratch (no allocations allowed)
__device__ float g_resid[BN * DN];
__device__ float g_quant[BN * DN];
__device__ float g_rnorm[BN];               // ||r||^2 per row (XLA-order fp32)
__device__ float g_wnorm[HN * KN];          // ||w||^2 per code row (XLA-order fp32)
__device__ float g_pbv[BN * NSPLIT];
__device__ int   g_pbi[BN * NSPLIT];
__device__ int   g_codes[BN * HN];

// ---------------------------------------------------------------------------
// XLA-style row reduction of sum(x*x) over 128 elements:
// one warp: lane accumulates x[l], x[l+32], x[l+64], x[l+96] sequentially with
// SEPARATE mul/add roundings (no FMA), then shfl-down tree 16,8,4,2,1.
__device__ __forceinline__ float row_sumsq_xla(const float* __restrict__ x, int lane) {
    float acc = 0.0f;
    #pragma unroll
    for (int i = 0; i < 4; i++) {
        float v = x[lane + 32 * i];
        acc = __fadd_rn(acc, __fmul_rn(v, v));
    }
    #pragma unroll
    for (int o = 16; o; o >>= 1)
        acc = __fadd_rn(acc, __shfl_down_sync(0xffffffffu, acc, o));
    return acc;   // valid in lane 0
}

// ||w||^2 per code row. One warp per row.
__global__ void wnorm_kernel(const float* __restrict__ emb) {
    int row  = blockIdx.x * 8 + (threadIdx.x >> 5);
    int lane = threadIdx.x & 31;
    if (row >= HN * KN) return;
    float s = row_sumsq_xla(emb + (size_t)row * DN, lane);
    if (lane == 0) g_wnorm[row] = s;
}

// ||r||^2 per row. One warp per row.
__global__ void rnorm_kernel() {
    int row  = blockIdx.x * 8 + (threadIdx.x >> 5);
    int lane = threadIdx.x & 31;
    if (row >= BN) return;
    float s = row_sumsq_xla(g_resid + (size_t)row * DN, lane);
    if (lane == 0) g_rnorm[row] = s;
}

// ---------------------------------------------------------------------------
__global__ void init_kernel(const float* __restrict__ in) {
    int i = blockIdx.x * blockDim.x + threadIdx.x;
    if (i < BN * DN) { g_resid[i] = in[i]; g_quant[i] = 0.0f; }
}

// ---------------------------------------------------------------------------
// 128x128 fp32 tile GEMM, exact fp32. Per-output dot is an FFMA chain with
// k ascending (matches cublas SGEMM). Score replicates the reference's fp32
// rounding events: s = fadd(rn, wn) - 2*dot  (2*dot exact, one final round at
// |s|~128 -> reproduces the reference's coarse-grid ties). argmin, ties ->
// lowest code index (== jnp.argmax first-max of the negation).
__global__ __launch_bounds__(256)
void argmax_kernel(const float* __restrict__ emb, int h) {
    __shared__ float As[32][129];   // [d][row]
    __shared__ float Bs[32][129];   // [d][code]

    const float* W  = emb + (size_t)h * KN * DN;
    const float* wn = g_wnorm + h * KN;

    const int mBase      = blockIdx.x * MT;
    const int kSplit     = KN / NSPLIT;          // 2048
    const int kSplitBase = blockIdx.y * kSplit;
    const int tid = threadIdx.x;
    const int tx = tid & 15, ty = tid >> 4;

    float bestv[8];
    int   besti[8];
    #pragma unroll
    for (int i = 0; i < 8; i++) { bestv[i] = FLT_MAX; besti[i] = 0; }

    float rn[8];
    #pragma unroll
    for (int i = 0; i < 8; i++) rn[i] = g_rnorm[mBase + i * 16 + ty];

    for (int kt = 0; kt < kSplit; kt += KT) {
        const int kBase = kSplitBase + kt;

        float acc[8][8];
        #pragma unroll
        for (int i = 0; i < 8; i++)
            #pragma unroll
            for (int j = 0; j < 8; j++) acc[i][j] = 0.0f;

        for (int dc = 0; dc < DN; dc += 32) {
            __syncthreads();
            #pragma unroll
            for (int it = 0; it < 4; it++) {
                int item = tid + 256 * it;       // 0..1023
                int r  = item >> 3;              // 0..127
                int d4 = item & 7;               // 0..7 (x4 floats)
                float4 va = *(const float4*)&g_resid[(size_t)(mBase + r) * DN + dc + d4 * 4];
                As[d4 * 4 + 0][r] = va.x; As[d4 * 4 + 1][r] = va.y;
                As[d4 * 4 + 2][r] = va.z; As[d4 * 4 + 3][r] = va.w;
                float4 vb = *(const float4*)&W[(size_t)(kBase + r) * DN + dc + d4 * 4];
                Bs[d4 * 4 + 0][r] = vb.x; Bs[d4 * 4 + 1][r] = vb.y;
                Bs[d4 * 4 + 2][r] = vb.z; Bs[d4 * 4 + 3][r] = vb.w;
            }
            __syncthreads();

            #pragma unroll
            for (int d = 0; d < 32; d++) {
                float a[8], b[8];
                #pragma unroll
                for (int i = 0; i < 8; i++) a[i] = As[d][i * 16 + ty];
                #pragma unroll
                for (int j = 0; j < 8; j++) b[j] = Bs[d][j * 16 + tx];
                #pragma unroll
                for (int i = 0; i < 8; i++)
                    #pragma unroll
                    for (int j = 0; j < 8; j++)
                        acc[i][j] = __fmaf_rn(a[i], b[j], acc[i][j]);  // FFMA chain, k ascending
            }
        }

        #pragma unroll
        for (int j = 0; j < 8; j++) {
            int   kk = kBase + j * 16 + tx;
            float w2 = wn[kk];
            #pragma unroll
            for (int i = 0; i < 8; i++) {
                // reference rounding events: t = rn + wn (round); u = 2*dot (exact);
                // s = t - u (round at |s| ~ 128 -> coarse-grid ties)
                float t = __fadd_rn(rn[i], w2);
                float s = __fsub_rn(t, __fmul_rn(2.0f, acc[i][j]));
                if (s < bestv[i]) { bestv[i] = s; besti[i] = kk; }  // strict: keeps lowest idx
            }
        }
    }

    // cross-thread reduction per row (tx lanes hold disjoint ascending ranges)
    __syncthreads();
    float* sv = &As[0][0];
    int*   si = (int*)&Bs[0][0];
    #pragma unroll
    for (int i = 0; i < 8; i++) {
        int row = i * 16 + ty;
        sv[row * 16 + tx] = bestv[i];
        si[row * 16 + tx] = besti[i];
    }
    __syncthreads();
    if (tid < 128) {
        float bv = FLT_MAX; int bi = 0x7fffffff;
        #pragma unroll
        for (int t = 0; t < 16; t++) {
            float v = sv[tid * 16 + t]; int id = si[tid * 16 + t];
            if (v < bv || (v == bv && id < bi)) { bv = v; bi = id; }
        }
        g_pbv[(size_t)(mBase + tid) * NSPLIT + blockIdx.y] = bv;
        g_pbi[(size_t)(mBase + tid) * NSPLIT + blockIdx.y] = bi;
    }
}

// ---------------------------------------------------------------------------
// Reduce split partials (min, lowest index), gather W[c], update resid/quant.
__global__ void update_kernel(const float* __restrict__ emb, int h) {
    int row = blockIdx.x;     // BN blocks, 128 threads
    __shared__ int sc;
    if (threadIdx.x == 0) {
        float bv = FLT_MAX; int bi = 0x7fffffff;
        #pragma unroll
        for (int t = 0; t < NSPLIT; t++) {
            float v = g_pbv[(size_t)row * NSPLIT + t];
            int  id = g_pbi[(size_t)row * NSPLIT + t];
            if (v < bv || (v == bv && id < bi)) { bv = v; bi = id; }
        }
        g_codes[row * HN + h] = bi;
        sc = bi;
    }
    __syncthreads();
    int c = sc;
    float q = emb[(size_t)h * KN * DN + (size_t)c * DN + threadIdx.x];
    g_resid[(size_t)row * DN + threadIdx.x] = __fsub_rn(g_resid[(size_t)row * DN + threadIdx.x], q);
    g_quant[(size_t)row * DN + threadIdx.x] = __fadd_rn(g_quant[(size_t)row * DN + threadIdx.x], q);
}

// ---------------------------------------------------------------------------
// Output: loss[BN]=0, quantized[BN*DN], codes[BN*HN] as float.
__global__ void pack_kernel(float* __restrict__ out) {
    int i = blockIdx.x * blockDim.x + threadIdx.x;
    const int q0 = BN;
    const int c0 = BN + BN * DN;
    const int tot = c0 + BN * HN;
    if (i >= tot) return;
    if (i < q0)       out[i] = 0.0f;
    else if (i < c0)  out[i] = g_quant[i - q0];
    else              out[i] = (float)g_codes[i - c0];
}

// ---------------------------------------------------------------------------
extern "C" void kernel_launch(void* const* d_in, const int* in_sizes, int n_in,
                              void* d_out, int out_size) {
    const float* inputs = (const float*)d_in[0];   // (4096,1,128) fp32
    const float* emb    = (const float*)d_in[1];   // (3,32768,128) fp32
    float* out = (float*)d_out;

    wnorm_kernel<<<(HN * KN) / 8, 256>>>(emb);
    init_kernel<<<(BN * DN + 255) / 256, 256>>>(inputs);

    for (int h = 0; h < HN; h++) {
        rnorm_kernel<<<BN / 8, 256>>>();           // XLA-order ||r||^2 of current resid
        dim3 grid(BN / MT, NSPLIT);
        argmax_kernel<<<grid, 256>>>(emb, h);
        update_kernel<<<BN, 128>>>(emb, h);
    }

    const int tot = BN + BN * DN + BN * HN;
    pack_kernel<<<(tot + 255) / 256, 256>>>(out);
}

// round 5
// speedup vs baseline: 1.1282x; 1.1282x over previous
#include <cuda_runtime.h>
#include <float.h>

#define BN 4096
#define KN 32768
#define DN 128
#define HN 3
#define NSPLIT 16
#define MT 128
#define KT 128

// scratch (no allocations allowed)
__device__ float g_resid[BN * DN];
__device__ float g_quant[BN * DN];
__device__ float g_rnorm[BN];               // ||r||^2 per row (XLA-order fp32)
__device__ float g_wnorm[HN * KN];          // ||w||^2 per code row (XLA-order fp32)
__device__ float g_pbv[BN * NSPLIT];
__device__ int   g_pbi[BN * NSPLIT];
__device__ int   g_codes[BN * HN];

// Packed dual fp32 FMA (FFMA2). Each half is an independent IEEE fp32 FMA —
// bitwise identical to two scalar __fmaf_rn, so the k-ascending accumulation
// chain semantics are unchanged.
__device__ __forceinline__ void ffma2(unsigned long long& d,
                                      unsigned long long a,
                                      unsigned long long b) {
    asm("fma.rn.f32x2 %0, %1, %2, %3;" : "=l"(d) : "l"(a), "l"(b), "l"(d));
}

// ---------------------------------------------------------------------------
// XLA-style row reduction of sum(x*x) over 128 elements (separate mul/add
// roundings, shfl-down tree). Matches the reference's norm bit-for-bit.
__device__ __forceinline__ float row_sumsq_xla(const float* __restrict__ x, int lane) {
    float acc = 0.0f;
    #pragma unroll
    for (int i = 0; i < 4; i++) {
        float v = x[lane + 32 * i];
        acc = __fadd_rn(acc, __fmul_rn(v, v));
    }
    #pragma unroll
    for (int o = 16; o; o >>= 1)
        acc = __fadd_rn(acc, __shfl_down_sync(0xffffffffu, acc, o));
    return acc;
}

__global__ void wnorm_kernel(const float* __restrict__ emb) {
    int row  = blockIdx.x * 8 + (threadIdx.x >> 5);
    int lane = threadIdx.x & 31;
    if (row >= HN * KN) return;
    float s = row_sumsq_xla(emb + (size_t)row * DN, lane);
    if (lane == 0) g_wnorm[row] = s;
}

__global__ void rnorm_kernel() {
    int row  = blockIdx.x * 8 + (threadIdx.x >> 5);
    int lane = threadIdx.x & 31;
    if (row >= BN) return;
    float s = row_sumsq_xla(g_resid + (size_t)row * DN, lane);
    if (lane == 0) g_rnorm[row] = s;
}

// ---------------------------------------------------------------------------
__global__ void init_kernel(const float* __restrict__ in) {
    int i = blockIdx.x * blockDim.x + threadIdx.x;
    if (i < BN * DN) { g_resid[i] = in[i]; g_quant[i] = 0.0f; }
}

// ---------------------------------------------------------------------------
// 128x128 fp32 tile GEMM using packed FFMA2 (2x fp32 FMA lanes/instr).
// Thread (tx,ty): rows i*16+ty (i=0..7); codes kBase + p*32 + 2*tx + {0,1}
// (p=0..3) as packed pairs -> conflict-free LDS.64 on B, duplicated-A LDS.64.
// Score replicates the reference's fp32 rounding events exactly:
// s = fsub(fadd(rn, wn), 2*dot). argmin, ties -> lowest code index.
__global__ __launch_bounds__(256, 2)
void argmax_kernel(const float* __restrict__ emb, int h) {
    __shared__ float2 As2[32][129];  // [d][row], value duplicated {v,v}
    __shared__ float  Bs[32][130];   // [d][code], 130 keeps rows 8B-aligned

    const float* W  = emb + (size_t)h * KN * DN;
    const float* wn = g_wnorm + h * KN;

    const int mBase      = blockIdx.x * MT;
    const int kSplit     = KN / NSPLIT;          // 2048
    const int kSplitBase = blockIdx.y * kSplit;
    const int tid = threadIdx.x;
    const int tx = tid & 15, ty = tid >> 4;

    float bestv[8];
    int   besti[8];
    #pragma unroll
    for (int i = 0; i < 8; i++) { bestv[i] = FLT_MAX; besti[i] = 0; }

    float rn[8];
    #pragma unroll
    for (int i = 0; i < 8; i++) rn[i] = g_rnorm[mBase + i * 16 + ty];

    for (int kt = 0; kt < kSplit; kt += KT) {
        const int kBase = kSplitBase + kt;

        unsigned long long acc2[8][4];   // [row i][code pair p]
        #pragma unroll
        for (int i = 0; i < 8; i++)
            #pragma unroll
            for (int p = 0; p < 4; p++) acc2[i][p] = 0ull;

        for (int dc = 0; dc < DN; dc += 32) {
            __syncthreads();
            #pragma unroll
            for (int it = 0; it < 4; it++) {
                int item = tid + 256 * it;       // 0..1023
                int r  = item >> 3;              // 0..127
                int d4 = item & 7;               // 0..7 (x4 floats)
                float4 va = *(const float4*)&g_resid[(size_t)(mBase + r) * DN + dc + d4 * 4];
                As2[d4 * 4 + 0][r] = make_float2(va.x, va.x);
                As2[d4 * 4 + 1][r] = make_float2(va.y, va.y);
                As2[d4 * 4 + 2][r] = make_float2(va.z, va.z);
                As2[d4 * 4 + 3][r] = make_float2(va.w, va.w);
                float4 vb = *(const float4*)&W[(size_t)(kBase + r) * DN + dc + d4 * 4];
                Bs[d4 * 4 + 0][r] = vb.x; Bs[d4 * 4 + 1][r] = vb.y;
                Bs[d4 * 4 + 2][r] = vb.z; Bs[d4 * 4 + 3][r] = vb.w;
            }
            __syncthreads();

            #pragma unroll
            for (int d = 0; d < 32; d++) {
                unsigned long long a2[8], b2[4];
                #pragma unroll
                for (int i = 0; i < 8; i++)
                    a2[i] = *(const unsigned long long*)&As2[d][i * 16 + ty];
                #pragma unroll
                for (int p = 0; p < 4; p++)
                    b2[p] = *(const unsigned long long*)&Bs[d][p * 32 + tx * 2];
                #pragma unroll
                for (int i = 0; i < 8; i++)
                    #pragma unroll
                    for (int p = 0; p < 4; p++)
                        ffma2(acc2[i][p], a2[i], b2[p]);   // k-ascending chain per output
            }
        }

        #pragma unroll
        for (int p = 0; p < 4; p++) {
            int   kk = kBase + p * 32 + tx * 2;
            float w2a = wn[kk];
            float w2b = wn[kk + 1];
            #pragma unroll
            for (int i = 0; i < 8; i++) {
                float dlo = __uint_as_float((unsigned)(acc2[i][p] & 0xffffffffull));
                float dhi = __uint_as_float((unsigned)(acc2[i][p] >> 32));
                float t  = __fadd_rn(rn[i], w2a);
                float s  = __fsub_rn(t, __fmul_rn(2.0f, dlo));
                if (s < bestv[i]) { bestv[i] = s; besti[i] = kk; }
                float t2 = __fadd_rn(rn[i], w2b);
                float s2 = __fsub_rn(t2, __fmul_rn(2.0f, dhi));
                if (s2 < bestv[i]) { bestv[i] = s2; besti[i] = kk + 1; }
            }
        }
    }

    // cross-thread reduction per row (tx lanes hold disjoint code sets)
    __syncthreads();
    float* sv = (float*)&Bs[0][0];       // 128*16 floats = 8KB, fits
    int*   si = (int*)&As2[0][0];
    #pragma unroll
    for (int i = 0; i < 8; i++) {
        int row = i * 16 + ty;
        sv[row * 16 + tx] = bestv[i];
        si[row * 16 + tx] = besti[i];
    }
    __syncthreads();
    if (tid < 128) {
        float bv = FLT_MAX; int bi = 0x7fffffff;
        #pragma unroll
        for (int t = 0; t < 16; t++) {
            float v = sv[tid * 16 + t]; int id = si[tid * 16 + t];
            if (v < bv || (v == bv && id < bi)) { bv = v; bi = id; }
        }
        g_pbv[(size_t)(mBase + tid) * NSPLIT + blockIdx.y] = bv;
        g_pbi[(size_t)(mBase + tid) * NSPLIT + blockIdx.y] = bi;
    }
}

// ---------------------------------------------------------------------------
__global__ void update_kernel(const float* __restrict__ emb, int h) {
    int row = blockIdx.x;     // BN blocks, 128 threads
    __shared__ int sc;
    if (threadIdx.x == 0) {
        float bv = FLT_MAX; int bi = 0x7fffffff;
        #pragma unroll
        for (int t = 0; t < NSPLIT; t++) {
            float v = g_pbv[(size_t)row * NSPLIT + t];
            int  id = g_pbi[(size_t)row * NSPLIT + t];
            if (v < bv || (v == bv && id < bi)) { bv = v; bi = id; }
        }
        g_codes[row * HN + h] = bi;
        sc = bi;
    }
    __syncthreads();
    int c = sc;
    float q = emb[(size_t)h * KN * DN + (size_t)c * DN + threadIdx.x];
    g_resid[(size_t)row * DN + threadIdx.x] = __fsub_rn(g_resid[(size_t)row * DN + threadIdx.x], q);
    g_quant[(size_t)row * DN + threadIdx.x] = __fadd_rn(g_quant[(size_t)row * DN + threadIdx.x], q);
}

// ---------------------------------------------------------------------------
__global__ void pack_kernel(float* __restrict__ out) {
    int i = blockIdx.x * blockDim.x + threadIdx.x;
    const int q0 = BN;
    const int c0 = BN + BN * DN;
    const int tot = c0 + BN * HN;
    if (i >= tot) return;
    if (i < q0)       out[i] = 0.0f;
    else if (i < c0)  out[i] = g_quant[i - q0];
    else              out[i] = (float)g_codes[i - c0];
}

// ---------------------------------------------------------------------------
extern "C" void kernel_launch(void* const* d_in, const int* in_sizes, int n_in,
                              void* d_out, int out_size) {
    const float* inputs = (const float*)d_in[0];   // (4096,1,128) fp32
    const float* emb    = (const float*)d_in[1];   // (3,32768,128) fp32
    float* out = (float*)d_out;

    wnorm_kernel<<<(HN * KN) / 8, 256>>>(emb);
    init_kernel<<<(BN * DN + 255) / 256, 256>>>(inputs);

    for (int h = 0; h < HN; h++) {
        rnorm_kernel<<<BN / 8, 256>>>();           // XLA-order ||r||^2 of current resid
        dim3 grid(BN / MT, NSPLIT);
        argmax_kernel<<<grid, 256>>>(emb, h);
        update_kernel<<<BN, 128>>>(emb, h);
    }

    const int tot = BN + BN * DN + BN * HN;
    pack_kernel<<<(tot + 255) / 256, 256>>>(out);
}

// round 6
// speedup vs baseline: 1.4302x; 1.2677x over previous
#include <cuda_runtime.h>
#include <float.h>

#define BN 4096
#define KN 32768
#define DN 128
#define HN 3
#define NSPLIT 32
#define MT 128
#define KT 256
#define DC 32
#define ASTRIDE 133          // A smem row stride (floats)
#define BSTRIDE 260          // B smem row stride (floats, mult of 4 for LDS.128)

// scratch (no allocations allowed)
__device__ float g_resid[BN * DN];
__device__ float g_quant[BN * DN];
__device__ float g_rnorm[BN];               // ||r||^2 per row (XLA-order fp32)
__device__ float g_wnorm[HN * KN];          // ||w||^2 per code row (XLA-order fp32)
__device__ float g_pbv[BN * NSPLIT];
__device__ int   g_pbi[BN * NSPLIT];
__device__ int   g_codes[BN * HN];

// Packed dual fp32 FMA. Each half is an independent IEEE fp32 FMA — bitwise
// identical to scalar __fmaf_rn, so k-ascending chain semantics are unchanged.
__device__ __forceinline__ void ffma2(unsigned long long& d,
                                      unsigned long long a,
                                      unsigned long long b) {
    asm("fma.rn.f32x2 %0, %1, %2, %3;" : "=l"(d) : "l"(a), "l"(b), "l"(d));
}
__device__ __forceinline__ unsigned long long splat2(float v) {
    unsigned long long r; unsigned u = __float_as_uint(v);
    asm("mov.b64 %0, {%1, %1};" : "=l"(r) : "r"(u));
    return r;
}
__device__ __forceinline__ unsigned long long pack2(float x, float y) {
    unsigned long long r;
    asm("mov.b64 %0, {%1, %2};" : "=l"(r) : "r"(__float_as_uint(x)), "r"(__float_as_uint(y)));
    return r;
}

// ---------------------------------------------------------------------------
// XLA-style row reduction of sum(x*x): separate mul/add roundings + shfl tree.
__device__ __forceinline__ float row_sumsq_xla(const float* __restrict__ x, int lane) {
    float acc = 0.0f;
    #pragma unroll
    for (int i = 0; i < 4; i++) {
        float v = x[lane + 32 * i];
        acc = __fadd_rn(acc, __fmul_rn(v, v));
    }
    #pragma unroll
    for (int o = 16; o; o >>= 1)
        acc = __fadd_rn(acc, __shfl_down_sync(0xffffffffu, acc, o));
    return acc;
}

__global__ void wnorm_kernel(const float* __restrict__ emb) {
    int row  = blockIdx.x * 8 + (threadIdx.x >> 5);
    int lane = threadIdx.x & 31;
    if (row >= HN * KN) return;
    float s = row_sumsq_xla(emb + (size_t)row * DN, lane);
    if (lane == 0) g_wnorm[row] = s;
}

__global__ void rnorm_kernel() {
    int row  = blockIdx.x * 8 + (threadIdx.x >> 5);
    int lane = threadIdx.x & 31;
    if (row >= BN) return;
    float s = row_sumsq_xla(g_resid + (size_t)row * DN, lane);
    if (lane == 0) g_rnorm[row] = s;
}

// ---------------------------------------------------------------------------
__global__ void init_kernel(const float* __restrict__ in) {
    int i = blockIdx.x * blockDim.x + threadIdx.x;
    if (i < BN * DN) { g_resid[i] = in[i]; g_quant[i] = 0.0f; }
}

// ---------------------------------------------------------------------------
// 128-row x 256-code tile GEMM, packed FFMA2.
// A (resid tile) preloaded ONCE per CTA, scalar [d][row], splatted at use.
// B chunked 32-d at a time, stored q-interleaved so each thread's 16 codes
// (tx*16..tx*16+15) are read as 4 conflict-free LDS.128.
// Score replicates reference rounding: s = fsub(fadd(rn,wn), 2*dot); argmin,
// strict < => lowest code index on ties.
__global__ __launch_bounds__(256)
void argmax_kernel(const float* __restrict__ emb, int h) {
    extern __shared__ float smem[];
    float* Asc = smem;                       // [DN][ASTRIDE]
    float* Bs  = smem + DN * ASTRIDE;        // [DC][BSTRIDE]

    const float* W  = emb + (size_t)h * KN * DN;
    const float* wn = g_wnorm + h * KN;

    const int mBase      = blockIdx.x * MT;
    const int kSplit     = KN / NSPLIT;          // 1024
    const int kSplitBase = blockIdx.y * kSplit;
    const int tid = threadIdx.x;
    const int tx = tid & 15, ty = tid >> 4;

    // ---- preload A (all 128 d) once ----
    #pragma unroll
    for (int it = 0; it < 16; it++) {
        int item = tid + 256 * it;           // 0..4095
        int r  = item >> 5;                  // 0..127
        int d4 = item & 31;                  // 0..31
        float4 va = *(const float4*)&g_resid[(size_t)(mBase + r) * DN + d4 * 4];
        Asc[(d4 * 4 + 0) * ASTRIDE + r] = va.x;
        Asc[(d4 * 4 + 1) * ASTRIDE + r] = va.y;
        Asc[(d4 * 4 + 2) * ASTRIDE + r] = va.z;
        Asc[(d4 * 4 + 3) * ASTRIDE + r] = va.w;
    }

    float bestv[8];
    int   besti[8];
    #pragma unroll
    for (int i = 0; i < 8; i++) { bestv[i] = FLT_MAX; besti[i] = 0; }

    float rn[8];
    #pragma unroll
    for (int i = 0; i < 8; i++) rn[i] = g_rnorm[mBase + i * 16 + ty];

    for (int kt = 0; kt < kSplit; kt += KT) {
        const int kBase = kSplitBase + kt;

        unsigned long long acc2[8][8];   // [row i][code pair p], codes tx*16+2p+{0,1}
        #pragma unroll
        for (int i = 0; i < 8; i++)
            #pragma unroll
            for (int p = 0; p < 8; p++) acc2[i][p] = 0ull;

        for (int dc = 0; dc < DN; dc += DC) {
            __syncthreads();   // previous chunk's reads done
            // load B chunk: 256 codes x 32 d, q-interleaved columns:
            // word(c) = ((c>>2)&3)*64 + (c>>4)*4 + (c&3)
            #pragma unroll
            for (int it = 0; it < 8; it++) {
                int item = tid + 256 * it;   // 0..2047
                int c  = item >> 3;          // 0..255
                int d4 = item & 7;           // 0..7
                float4 vb = *(const float4*)&W[(size_t)(kBase + c) * DN + dc + d4 * 4];
                int widx = ((c >> 2) & 3) * 64 + (c >> 4) * 4 + (c & 3);
                Bs[(d4 * 4 + 0) * BSTRIDE + widx] = vb.x;
                Bs[(d4 * 4 + 1) * BSTRIDE + widx] = vb.y;
                Bs[(d4 * 4 + 2) * BSTRIDE + widx] = vb.z;
                Bs[(d4 * 4 + 3) * BSTRIDE + widx] = vb.w;
            }
            __syncthreads();

            #pragma unroll 8
            for (int dd = 0; dd < DC; dd++) {
                const int d = dc + dd;
                unsigned long long a2[8];
                #pragma unroll
                for (int i = 0; i < 8; i++)
                    a2[i] = splat2(Asc[d * ASTRIDE + i * 16 + ty]);
                unsigned long long b2[8];
                #pragma unroll
                for (int q = 0; q < 4; q++) {
                    float4 f = *(const float4*)&Bs[dd * BSTRIDE + q * 64 + tx * 4];
                    b2[q * 2 + 0] = pack2(f.x, f.y);   // codes tx*16+q*4+{0,1}
                    b2[q * 2 + 1] = pack2(f.z, f.w);   // codes tx*16+q*4+{2,3}
                }
                #pragma unroll
                for (int i = 0; i < 8; i++)
                    #pragma unroll
                    for (int p = 0; p < 8; p++)
                        ffma2(acc2[i][p], a2[i], b2[p]);   // k-ascending chain
            }
        }

        // epilogue: reference rounding events, ascending code order
        #pragma unroll
        for (int p = 0; p < 8; p++) {
            int   kk  = kBase + tx * 16 + p * 2;
            float w2a = wn[kk];
            float w2b = wn[kk + 1];
            #pragma unroll
            for (int i = 0; i < 8; i++) {
                float dlo = __uint_as_float((unsigned)(acc2[i][p] & 0xffffffffull));
                float dhi = __uint_as_float((unsigned)(acc2[i][p] >> 32));
                float s  = __fsub_rn(__fadd_rn(rn[i], w2a), __fmul_rn(2.0f, dlo));
                if (s < bestv[i]) { bestv[i] = s; besti[i] = kk; }
                float s2 = __fsub_rn(__fadd_rn(rn[i], w2b), __fmul_rn(2.0f, dhi));
                if (s2 < bestv[i]) { bestv[i] = s2; besti[i] = kk + 1; }
            }
        }
    }

    // cross-thread reduction per row (tx lanes hold disjoint code sets)
    __syncthreads();
    float* sv = smem;                 // 2048 floats
    int*   si = (int*)(smem + 2048);  // 2048 ints
    #pragma unroll
    for (int i = 0; i < 8; i++) {
        int row = i * 16 + ty;
        sv[row * 16 + tx] = bestv[i];
        si[row * 16 + tx] = besti[i];
    }
    __syncthreads();
    if (tid < 128) {
        float bv = FLT_MAX; int bi = 0x7fffffff;
        #pragma unroll
        for (int t = 0; t < 16; t++) {
            float v = sv[tid * 16 + t]; int id = si[tid * 16 + t];
            if (v < bv || (v == bv && id < bi)) { bv = v; bi = id; }
        }
        g_pbv[(size_t)(mBase + tid) * NSPLIT + blockIdx.y] = bv;
        g_pbi[(size_t)(mBase + tid) * NSPLIT + blockIdx.y] = bi;
    }
}

// ---------------------------------------------------------------------------
__global__ void update_kernel(const float* __restrict__ emb, int h) {
    int row = blockIdx.x;     // BN blocks, 128 threads
    __shared__ int sc;
    if (threadIdx.x == 0) {
        float bv = FLT_MAX; int bi = 0x7fffffff;
        #pragma unroll
        for (int t = 0; t < NSPLIT; t++) {
            float v = g_pbv[(size_t)row * NSPLIT + t];
            int  id = g_pbi[(size_t)row * NSPLIT + t];
            if (v < bv || (v == bv && id < bi)) { bv = v; bi = id; }
        }
        g_codes[row * HN + h] = bi;
        sc = bi;
    }
    __syncthreads();
    int c = sc;
    float q = emb[(size_t)h * KN * DN + (size_t)c * DN + threadIdx.x];
    g_resid[(size_t)row * DN + threadIdx.x] = __fsub_rn(g_resid[(size_t)row * DN + threadIdx.x], q);
    g_quant[(size_t)row * DN + threadIdx.x] = __fadd_rn(g_quant[(size_t)row * DN + threadIdx.x], q);
}

// ---------------------------------------------------------------------------
__global__ void pack_kernel(float* __restrict__ out) {
    int i = blockIdx.x * blockDim.x + threadIdx.x;
    const int q0 = BN;
    const int c0 = BN + BN * DN;
    const int tot = c0 + BN * HN;
    if (i >= tot) return;
    if (i < q0)       out[i] = 0.0f;
    else if (i < c0)  out[i] = g_quant[i - q0];
    else              out[i] = (float)g_codes[i - c0];
}

// ---------------------------------------------------------------------------
extern "C" void kernel_launch(void* const* d_in, const int* in_sizes, int n_in,
                              void* d_out, int out_size) {
    const float* inputs = (const float*)d_in[0];   // (4096,1,128) fp32
    const float* emb    = (const float*)d_in[1];   // (3,32768,128) fp32
    float* out = (float*)d_out;

    const int smem_bytes = (DN * ASTRIDE + DC * BSTRIDE) * (int)sizeof(float); // ~101.4KB
    cudaFuncSetAttribute(argmax_kernel, cudaFuncAttributeMaxDynamicSharedMemorySize, smem_bytes);

    wnorm_kernel<<<(HN * KN) / 8, 256>>>(emb);
    init_kernel<<<(BN * DN + 255) / 256, 256>>>(inputs);

    for (int h = 0; h < HN; h++) {
        rnorm_kernel<<<BN / 8, 256>>>();           // XLA-order ||r||^2 of current resid
        dim3 grid(BN / MT, NSPLIT);
        argmax_kernel<<<grid, 256, smem_bytes>>>(emb, h);
        update_kernel<<<BN, 128>>>(emb, h);
    }

    const int tot = BN + BN * DN + BN * HN;
    pack_kernel<<<(tot + 255) / 256, 256>>>(out);
}